// round 10
// baseline (speedup 1.0000x reference)
#include <cuda_runtime.h>
#include <cstdint>

// Problem constants
#define MROWS   65536
#define KDIM    48          // s_in = 32 + 16
#define NSPL    32          // spline groups per row
#define NB      33          // 2K+1 outputs per group (17 heights, 16 widths)
#define NPAD    36          // padded group width (36*4=144B, 16B-aligned for LDS.128)
#define NGRP    8           // spline groups per block (= warps per block)
#define BM      64          // rows per block
#define THREADS 256
#define WS_STRIDE (NGRP * NPAD)                 // 288 floats per k-row
#define AST     (BM + 2)                        // transposed A row: 64 rows + 2 pad
#define SMEM_FLOATS (KDIM * WS_STRIDE + KDIM * AST + WS_STRIDE)
#define SMEM_BYTES  (SMEM_FLOATS * 4)           // 69120 B -> 3 blocks/SM (207 KB)
// stash: 17*256*8 = 34816 B, overlays Ws (55296 B). ldbuf: 2048 B after stash.

// ---------- packed f32x2 helpers ----------
__device__ __forceinline__ unsigned long long pack2(float a) {
    unsigned long long r;
    asm("mov.b64 %0, {%1, %1};" : "=l"(r) : "f"(a));
    return r;
}
__device__ __forceinline__ void ffma2(unsigned long long& d,
                                      unsigned long long a,
                                      unsigned long long b) {
    asm("fma.rn.f32x2 %0, %1, %2, %0;" : "+l"(d) : "l"(a), "l"(b));
}

__device__ __forceinline__ float softplus_fast(float x) {
    // |x| is small here (bias + y, |y| ~ 0.5): direct form is stable.
    return __logf(1.0f + __expf(x)) + 0.001f;
}

// ---------- quadratic spline (per (m,n) pair), MUFU fast-math ----------
// getacc(p) returns packed pair (y[2p], y[2p+1]); y[0..16]=unnorm heights,
// y[17..32]=unnorm widths, y[33]=0 (pad).
template <typename F>
__device__ __forceinline__ float spline_eval(F getacc, float input, float& x_out) {
    float h[17], w[16];

    // heights: pairs p=0..7 -> y0..y15, plus p=8.lo -> y16
#pragma unroll
    for (int p = 0; p < 8; p++) {
        unsigned long long v = getacc(p);
        h[2 * p]     = softplus_fast(__uint_as_float((unsigned int)v));
        h[2 * p + 1] = softplus_fast(__uint_as_float((unsigned int)(v >> 32)));
    }
    unsigned long long v8 = getacc(8);
    h[16] = softplus_fast(__uint_as_float((unsigned int)v8));

    // widths: p=8.hi -> idx0 ; p=9..15 -> idx 1..14 ; p=16.lo -> idx15 (hi=pad)
    float esum;
    w[0] = __expf(__uint_as_float((unsigned int)(v8 >> 32)));
    esum = w[0];
#pragma unroll
    for (int p = 9; p <= 15; p++) {
        unsigned long long v = getacc(p);
        float e0 = __expf(__uint_as_float((unsigned int)v));
        float e1 = __expf(__uint_as_float((unsigned int)(v >> 32)));
        w[2 * p - 17] = e0;
        w[2 * p - 16] = e1;
        esum += e0 + e1;
    }
    {
        unsigned long long v = getacc(16);
        float e0 = __expf(__uint_as_float((unsigned int)v));
        w[15] = e0;
        esum += e0;
    }

    // widths = MIN_BW + (1 - 16*MIN_BW) * softmax
    float inv = __fdividef(1.0f, esum);
#pragma unroll
    for (int i = 0; i < 16; i++) w[i] = 0.001f + 0.984f * (w[i] * inv);

    // area (0.5 deferred into the divide) & normalized heights
    float area2 = 0.0f;
#pragma unroll
    for (int i = 0; i < 16; i++) area2 += (h[i] + h[i + 1]) * w[i];
    float hs = __fdividef(1.998f, area2);   // 2*(1 - MIN_BH)/area2
#pragma unroll
    for (int i = 0; i < 17; i++) h[i] = 0.001f + h[i] * hs;

    // scan: cumsums (0.5 deferred on C) + predicated bin select
    float L = 0.0f, C2 = 0.0f;
    float bl = 0.0f, bw = w[0], lcdf2 = 0.0f, hl = h[0], hr = h[1];
#pragma unroll
    for (int i = 1; i <= 15; i++) {
        L  += w[i - 1];
        C2 += (h[i - 1] + h[i]) * w[i - 1];
        if (input >= L) { bl = L; bw = w[i]; lcdf2 = C2; hl = h[i]; hr = h[i + 1]; }
    }

    float aq    = 0.5f * (hr - hl) * bw;
    float bq    = hl * bw;
    float alpha = __fdividef(input - bl, bw);
    float o = aq * alpha * alpha + bq * alpha + 0.5f * lcdf2;
    x_out = fminf(fmaxf(o, 0.0f), 1.0f);
    return __logf(alpha * (hr - hl) + hl);
}

// ---------- prep: zero log_det only (x[:, :32] written by main kernel) ----------
__global__ void prep_kernel(float* __restrict__ out) {
    int tid = blockIdx.x * blockDim.x + threadIdx.x;
    if (tid < MROWS / 4) {
        ((float4*)(out + (size_t)MROWS * 64))[tid] = make_float4(0.f, 0.f, 0.f, 0.f);
    }
}

// ---------- fused GEMM + spline ----------
// WARP = GROUP mapping: warp w owns spline group (g*8+w) for all 64 rows.
// All W smem loads are warp-uniform -> full 32-lane broadcast (1 wavefront).
__global__ void __launch_bounds__(THREADS, 3)
spline_main_kernel(const float* __restrict__ c, const float* __restrict__ z,
                   const float* __restrict__ W, const float* __restrict__ b,
                   float* __restrict__ out) {
    extern __shared__ float sm[];
    float* Ws = sm;                                   // [48][8][36]  W slice
    float* As = sm + KDIM * WS_STRIDE;                // [48][66]     A tile, TRANSPOSED [k][row]
    float* bs = As + KDIM * AST;                      // [8][36]      bias slice

    const int t       = threadIdx.x;
    const int g       = blockIdx.x;                   // n-group block (0..3)
    const int rowbase = blockIdx.y * BM;

    // W slice: cols [g*264, g*264+264), float4 gmem loads, scalar swizzled STS.
    for (int idx = t; idx < KDIM * 66; idx += THREADS) {
        int k  = idx / 66;
        int c4 = idx - k * 66;
        float4 v = *(const float4*)&W[(size_t)k * 1056 + g * (NGRP * NB) + c4 * 4];
        float e[4] = {v.x, v.y, v.z, v.w};
#pragma unroll
        for (int q = 0; q < 4; q++) {
            int cc = c4 * 4 + q;
            int ln = cc / NB;
            int j  = cc - ln * NB;
            Ws[k * WS_STRIDE + ln * NPAD + j] = e[q];
        }
    }
    for (int idx = t; idx < KDIM * NGRP * 3; idx += THREADS) {  // zero pad cols j=33,34,35
        int k  = idx / (NGRP * 3);
        int r  = idx - k * (NGRP * 3);
        int ln = r / 3, j = 33 + (r - ln * 3);
        Ws[k * WS_STRIDE + ln * NPAD + j] = 0.0f;
    }
    // bias (padded to 36)
    for (int idx = t; idx < WS_STRIDE; idx += THREADS) {
        int ln = idx / NPAD, j = idx - ln * NPAD;
        bs[idx] = (j < NB) ? b[g * (NGRP * NB) + ln * NB + j] : 0.0f;
    }
    // A tile TRANSPOSED: As[k][r]. Cols 0..31 of A = z[:,32:64], cols 32..47 = c.
    for (int idx = t; idx < BM * 8; idx += THREADS) {
        int q = idx / BM, r = idx - q * BM;        // lanes contiguous in r -> STS conflict-free
        float4 v = *(const float4*)&z[(size_t)(rowbase + r) * 64 + 32 + q * 4];
        As[(q * 4 + 0) * AST + r] = v.x;
        As[(q * 4 + 1) * AST + r] = v.y;
        As[(q * 4 + 2) * AST + r] = v.z;
        As[(q * 4 + 3) * AST + r] = v.w;
    }
    for (int idx = t; idx < BM * 4; idx += THREADS) {
        int q = idx / BM, r = idx - q * BM;
        float4 v = *(const float4*)&c[(size_t)(rowbase + r) * 16 + q * 4];
        As[(32 + q * 4 + 0) * AST + r] = v.x;
        As[(32 + q * 4 + 1) * AST + r] = v.y;
        As[(32 + q * 4 + 2) * AST + r] = v.z;
        As[(32 + q * 4 + 3) * AST + r] = v.w;
    }
    __syncthreads();

    // g==0 blocks write x[:, :32] = z2 straight from the As tile (replaces prep copy)
    if (g == 0) {
        int r = t >> 2;                        // 64 rows x 4 threads/row
        int c0 = (t & 3) * 8;                  // 8 consecutive cols each
        float vv[8];
#pragma unroll
        for (int q = 0; q < 8; q++) vv[q] = As[(c0 + q) * AST + r];
        float4* dst = (float4*)&out[(size_t)(rowbase + r) * 64 + c0];
        dst[0] = make_float4(vv[0], vv[1], vv[2], vv[3]);
        dst[1] = make_float4(vv[4], vv[5], vv[6], vv[7]);
    }

    const int w_id = t >> 5;         // warp = local group in [0,8)
    const int lane = t & 31;         // lane -> row slot
    const int r0 = lane * 2, r1 = r0 + 1;
    const int gn = g * NGRP + w_id;  // global spline index in [0,32)

    const float* wcol = Ws + w_id * NPAD;            // warp-uniform base
    const unsigned long long* b2 = (const unsigned long long*)(bs + w_id * NPAD);

    unsigned long long acc0[17], acc1[17];
#pragma unroll
    for (int p = 0; p < 17; p++) { acc0[p] = b2[p]; acc1[p] = b2[p]; }

#pragma unroll 4
    for (int k = 0; k < KDIM; k++) {
        // both rows in ONE LDS.64 (A transposed, rows contiguous)
        unsigned long long araw = *(const unsigned long long*)(As + k * AST + r0);
        float a0f = __uint_as_float((unsigned int)araw);
        float a1f = __uint_as_float((unsigned int)(araw >> 32));
        unsigned long long ap0 = pack2(a0f);
        unsigned long long ap1 = pack2(a1f);
        const float* wrow = wcol + k * WS_STRIDE;
        // 8 x LDS.128 + 1 x LDS.64, ALL warp-uniform -> broadcast, 1 wf each
#pragma unroll
        for (int p8 = 0; p8 < 8; p8++) {
            ulonglong2 wv = *(const ulonglong2*)(wrow + p8 * 4);
            ffma2(acc0[2 * p8],     ap0, wv.x);
            ffma2(acc1[2 * p8],     ap1, wv.x);
            ffma2(acc0[2 * p8 + 1], ap0, wv.y);
            ffma2(acc1[2 * p8 + 1], ap1, wv.y);
        }
        unsigned long long wt = *(const unsigned long long*)(wrow + 32);
        ffma2(acc0[16], ap0, wt);
        ffma2(acc1[16], ap1, wt);
    }

    const int row0 = rowbase + r0;
    const int row1 = rowbase + r1;
    // hoist spline inputs (LDG latency hides under stash STS)
    float zin0 = z[(size_t)row0 * 64 + gn];
    float zin1 = z[(size_t)row1 * 64 + gn];

    // ---- anti-spill: stash acc1 in SMEM (Ws region dead after this barrier) ----
    __syncthreads();                  // all GEMM reads of Ws/As + z2 writes retired
    unsigned long long* stash = (unsigned long long*)sm;   // 17*256*8 = 34816 B
    float* ldbuf = sm + 34816 / 4;                         // [8][64] floats, 2048 B
#pragma unroll
    for (int p = 0; p < 17; p++) stash[p * THREADS + t] = acc1[p];
    // each thread reads back only its own slots -> no barrier needed

    // spline row 0 (acc0 in registers, consumed during unpack)
    float x0, x1v;
    float ld0 = spline_eval([&](int p) { return acc0[p]; }, zin0, x0);
    out[(size_t)row0 * 64 + 32 + gn] = x0;

    // spline row 1 (acc streamed from SMEM stash)
    float ld1 = spline_eval([&](int p) { return stash[p * THREADS + t]; }, zin1, x1v);
    out[(size_t)row1 * 64 + 32 + gn] = x1v;

    // log_det: block-level reduction over the 8 warps (one STS.64 per thread),
    // then 64 lanes do one global atomic each (4 blocks still share a row).
    *(float2*)&ldbuf[w_id * BM + r0] = make_float2(ld0, ld1);
    __syncthreads();
    if (t < BM) {
        float s = 0.0f;
#pragma unroll
        for (int w = 0; w < NGRP; w++) s += ldbuf[w * BM + t];
        atomicAdd(&out[(size_t)MROWS * 64 + rowbase + t], s);
    }
}

extern "C" void kernel_launch(void* const* d_in, const int* in_sizes, int n_in,
                              void* d_out, int out_size) {
    const float* c = (const float*)d_in[0];   // (65536, 16)
    const float* z = (const float*)d_in[1];   // (65536, 64)
    const float* W = (const float*)d_in[2];   // (48, 1056)
    const float* b = (const float*)d_in[3];   // (1056,)
    float* out = (float*)d_out;               // 65536*64 (x) + 65536 (log_det)

    cudaFuncSetAttribute(spline_main_kernel,
                         cudaFuncAttributeMaxDynamicSharedMemorySize, SMEM_BYTES);

    prep_kernel<<<(MROWS / 4 + 255) / 256, 256>>>(out);

    dim3 grid(NSPL / NGRP, MROWS / BM);       // (4, 1024)
    spline_main_kernel<<<grid, THREADS, SMEM_BYTES>>>(c, z, W, b, out);
}

// round 11
// speedup vs baseline: 1.3684x; 1.3684x over previous
#include <cuda_runtime.h>
#include <cstdint>

// Problem constants
#define MROWS   65536
#define KDIM    48          // s_in = 32 + 16
#define NSPL    32          // spline groups per row
#define NB      33          // 2K+1 outputs per group (17 heights, 16 widths)
#define NPAD    36          // padded group width (36*4=144B, 16B-aligned for LDS.128)
#define NGRP    8           // spline groups per block (= warps per block)
#define BM      64          // rows per block
#define THREADS 256
#define WS_STRIDE (NGRP * NPAD)                 // 288 floats per k-row
#define AST     (BM + 2)                        // transposed A row: 64 rows + 2 pad
// Dedicated regions (no overlay -> no mid-kernel barrier):
// Ws 13824f | As 3168f | bs 288f | stash 8704f (17*256 u64) | ldbuf 512f
#define WS_F    (KDIM * WS_STRIDE)              // 13824
#define AS_F    (KDIM * AST)                    // 3168
#define BS_F    WS_STRIDE                       // 288
#define STASH_F (17 * THREADS * 2)              // 8704 floats (u64 slots)
#define LDBUF_F (NGRP * BM)                     // 512
#define SMEM_FLOATS (WS_F + AS_F + BS_F + STASH_F + LDBUF_F)
#define SMEM_BYTES  (SMEM_FLOATS * 4)           // 105984 B -> 2 blocks/SM (212 KB)

// ---------- packed f32x2 helpers ----------
__device__ __forceinline__ unsigned long long pack2(float a) {
    unsigned long long r;
    asm("mov.b64 %0, {%1, %1};" : "=l"(r) : "f"(a));
    return r;
}
__device__ __forceinline__ void ffma2(unsigned long long& d,
                                      unsigned long long a,
                                      unsigned long long b) {
    asm("fma.rn.f32x2 %0, %1, %2, %0;" : "+l"(d) : "l"(a), "l"(b));
}

__device__ __forceinline__ float softplus_fast(float x) {
    // |x| is small here (~|y| <= 2): direct form is stable with MUFU.
    return __logf(1.0f + __expf(x)) + 0.001f;
}

// ---------- quadratic spline (per (m,n) pair), MUFU fast-math ----------
// getacc(p) returns packed pair (y[2p], y[2p+1]); y[0..16]=unnorm heights,
// y[17..32]=unnorm widths, y[33]=0 (pad).
template <typename F>
__device__ __forceinline__ float spline_eval(F getacc, float input, float& x_out) {
    float h[17], w[16];

    // heights: pairs p=0..7 -> y0..y15, plus p=8.lo -> y16
#pragma unroll
    for (int p = 0; p < 8; p++) {
        unsigned long long v = getacc(p);
        h[2 * p]     = softplus_fast(__uint_as_float((unsigned int)v));
        h[2 * p + 1] = softplus_fast(__uint_as_float((unsigned int)(v >> 32)));
    }
    unsigned long long v8 = getacc(8);
    h[16] = softplus_fast(__uint_as_float((unsigned int)v8));

    // widths: p=8.hi -> idx0 ; p=9..15 -> idx 1..14 ; p=16.lo -> idx15 (hi=pad)
    float esum;
    w[0] = __expf(__uint_as_float((unsigned int)(v8 >> 32)));
    esum = w[0];
#pragma unroll
    for (int p = 9; p <= 15; p++) {
        unsigned long long v = getacc(p);
        float e0 = __expf(__uint_as_float((unsigned int)v));
        float e1 = __expf(__uint_as_float((unsigned int)(v >> 32)));
        w[2 * p - 17] = e0;
        w[2 * p - 16] = e1;
        esum += e0 + e1;
    }
    {
        unsigned long long v = getacc(16);
        float e0 = __expf(__uint_as_float((unsigned int)v));
        w[15] = e0;
        esum += e0;
    }

    // widths = MIN_BW + (1 - 16*MIN_BW) * softmax
    float inv = __fdividef(1.0f, esum);
#pragma unroll
    for (int i = 0; i < 16; i++) w[i] = 0.001f + 0.984f * (w[i] * inv);

    // area (0.5 deferred into the divide) & normalized heights
    float area2 = 0.0f;
#pragma unroll
    for (int i = 0; i < 16; i++) area2 += (h[i] + h[i + 1]) * w[i];
    float hs = __fdividef(1.998f, area2);   // 2*(1 - MIN_BH)/area2
#pragma unroll
    for (int i = 0; i < 17; i++) h[i] = 0.001f + h[i] * hs;

    // scan: cumsums (0.5 deferred on C) + predicated bin select
    float L = 0.0f, C2 = 0.0f;
    float bl = 0.0f, bw = w[0], lcdf2 = 0.0f, hl = h[0], hr = h[1];
#pragma unroll
    for (int i = 1; i <= 15; i++) {
        L  += w[i - 1];
        C2 += (h[i - 1] + h[i]) * w[i - 1];
        if (input >= L) { bl = L; bw = w[i]; lcdf2 = C2; hl = h[i]; hr = h[i + 1]; }
    }

    float aq    = 0.5f * (hr - hl) * bw;
    float bq    = hl * bw;
    float alpha = __fdividef(input - bl, bw);
    float o = aq * alpha * alpha + bq * alpha + 0.5f * lcdf2;
    x_out = fminf(fmaxf(o, 0.0f), 1.0f);
    return __logf(alpha * (hr - hl) + hl);
}

// ---------- prep: zero log_det only (x[:, :32] written by main kernel) ----------
__global__ void prep_kernel(float* __restrict__ out) {
    int tid = blockIdx.x * blockDim.x + threadIdx.x;
    if (tid < MROWS / 4) {
        ((float4*)(out + (size_t)MROWS * 64))[tid] = make_float4(0.f, 0.f, 0.f, 0.f);
    }
}

// ---------- fused GEMM + spline ----------
// WARP = GROUP mapping: warp w owns spline group (g*8+w) for all 64 rows.
// All W smem loads are warp-uniform -> full 32-lane broadcast (1 wavefront).
// NO mid-kernel barrier: stash/ldbuf have dedicated SMEM, so each warp flows
// GEMM -> spline independently (cross-warp fma/MUFU/alu overlap).
__global__ void __launch_bounds__(THREADS, 2)
spline_main_kernel(const float* __restrict__ c, const float* __restrict__ z,
                   const float* __restrict__ W, const float* __restrict__ b,
                   float* __restrict__ out) {
    extern __shared__ float sm[];
    float* Ws = sm;                                   // [48][8][36]
    float* As = Ws + WS_F;                            // [48][66]  A tile, TRANSPOSED [k][row]
    float* bs = As + AS_F;                            // [8][36]
    unsigned long long* stash = (unsigned long long*)(bs + BS_F);   // [17][256]
    float* ldbuf = bs + BS_F + STASH_F;               // [8][64]

    const int t       = threadIdx.x;
    const int g       = blockIdx.x;                   // n-group block (0..3)
    const int rowbase = blockIdx.y * BM;

    // W slice: cols [g*264, g*264+264), float4 gmem loads, scalar swizzled STS.
    for (int idx = t; idx < KDIM * 66; idx += THREADS) {
        int k  = idx / 66;
        int c4 = idx - k * 66;
        float4 v = *(const float4*)&W[(size_t)k * 1056 + g * (NGRP * NB) + c4 * 4];
        float e[4] = {v.x, v.y, v.z, v.w};
#pragma unroll
        for (int q = 0; q < 4; q++) {
            int cc = c4 * 4 + q;
            int ln = cc / NB;
            int j  = cc - ln * NB;
            Ws[k * WS_STRIDE + ln * NPAD + j] = e[q];
        }
    }
    for (int idx = t; idx < KDIM * NGRP * 3; idx += THREADS) {  // zero pad cols j=33,34,35
        int k  = idx / (NGRP * 3);
        int r  = idx - k * (NGRP * 3);
        int ln = r / 3, j = 33 + (r - ln * 3);
        Ws[k * WS_STRIDE + ln * NPAD + j] = 0.0f;
    }
    // bias (padded to 36)
    for (int idx = t; idx < WS_STRIDE; idx += THREADS) {
        int ln = idx / NPAD, j = idx - ln * NPAD;
        bs[idx] = (j < NB) ? b[g * (NGRP * NB) + ln * NB + j] : 0.0f;
    }
    // A tile TRANSPOSED: As[k][r]. Cols 0..31 of A = z[:,32:64], cols 32..47 = c.
    for (int idx = t; idx < BM * 8; idx += THREADS) {
        int q = idx / BM, r = idx - q * BM;        // lanes contiguous in r -> STS conflict-free
        float4 v = *(const float4*)&z[(size_t)(rowbase + r) * 64 + 32 + q * 4];
        As[(q * 4 + 0) * AST + r] = v.x;
        As[(q * 4 + 1) * AST + r] = v.y;
        As[(q * 4 + 2) * AST + r] = v.z;
        As[(q * 4 + 3) * AST + r] = v.w;
    }
    for (int idx = t; idx < BM * 4; idx += THREADS) {
        int q = idx / BM, r = idx - q * BM;
        float4 v = *(const float4*)&c[(size_t)(rowbase + r) * 16 + q * 4];
        As[(32 + q * 4 + 0) * AST + r] = v.x;
        As[(32 + q * 4 + 1) * AST + r] = v.y;
        As[(32 + q * 4 + 2) * AST + r] = v.z;
        As[(32 + q * 4 + 3) * AST + r] = v.w;
    }
    __syncthreads();

    // g==0 blocks write x[:, :32] = z2 straight from the As tile (replaces prep copy)
    if (g == 0) {
        int r = t >> 2;                        // 64 rows x 4 threads/row
        int c0 = (t & 3) * 8;                  // 8 consecutive cols each
        float vv[8];
#pragma unroll
        for (int q = 0; q < 8; q++) vv[q] = As[(c0 + q) * AST + r];
        float4* dst = (float4*)&out[(size_t)(rowbase + r) * 64 + c0];
        dst[0] = make_float4(vv[0], vv[1], vv[2], vv[3]);
        dst[1] = make_float4(vv[4], vv[5], vv[6], vv[7]);
    }

    const int w_id = t >> 5;         // warp = local group in [0,8)
    const int lane = t & 31;         // lane -> row slot
    const int r0 = lane * 2, r1 = r0 + 1;
    const int gn = g * NGRP + w_id;  // global spline index in [0,32)

    const float* wcol = Ws + w_id * NPAD;            // warp-uniform base
    const unsigned long long* b2 = (const unsigned long long*)(bs + w_id * NPAD);

    unsigned long long acc0[17], acc1[17];
#pragma unroll
    for (int p = 0; p < 17; p++) { acc0[p] = b2[p]; acc1[p] = b2[p]; }

#pragma unroll 4
    for (int k = 0; k < KDIM; k++) {
        // both rows in ONE LDS.64 (A transposed, rows contiguous)
        unsigned long long araw = *(const unsigned long long*)(As + k * AST + r0);
        float a0f = __uint_as_float((unsigned int)araw);
        float a1f = __uint_as_float((unsigned int)(araw >> 32));
        unsigned long long ap0 = pack2(a0f);
        unsigned long long ap1 = pack2(a1f);
        const float* wrow = wcol + k * WS_STRIDE;
        // 8 x LDS.128 + 1 x LDS.64, ALL warp-uniform -> broadcast, 1 wf each
#pragma unroll
        for (int p8 = 0; p8 < 8; p8++) {
            ulonglong2 wv = *(const ulonglong2*)(wrow + p8 * 4);
            ffma2(acc0[2 * p8],     ap0, wv.x);
            ffma2(acc1[2 * p8],     ap1, wv.x);
            ffma2(acc0[2 * p8 + 1], ap0, wv.y);
            ffma2(acc1[2 * p8 + 1], ap1, wv.y);
        }
        unsigned long long wt = *(const unsigned long long*)(wrow + 32);
        ffma2(acc0[16], ap0, wt);
        ffma2(acc1[16], ap1, wt);
    }

    const int row0 = rowbase + r0;
    const int row1 = rowbase + r1;
    // hoist spline inputs (LDG latency hides under stash STS)
    float zin0 = z[(size_t)row0 * 64 + gn];
    float zin1 = z[(size_t)row1 * 64 + gn];

    // stash acc1 in dedicated SMEM (no barrier needed; own slots only)
#pragma unroll
    for (int p = 0; p < 17; p++) stash[p * THREADS + t] = acc1[p];

    // spline row 0 (acc0 in registers, consumed during unpack)
    float x0, x1v;
    float ld0 = spline_eval([&](int p) { return acc0[p]; }, zin0, x0);
    out[(size_t)row0 * 64 + 32 + gn] = x0;

    // spline row 1 (acc streamed from SMEM stash)
    float ld1 = spline_eval([&](int p) { return stash[p * THREADS + t]; }, zin1, x1v);
    out[(size_t)row1 * 64 + 32 + gn] = x1v;

    // log_det: block-level reduction over the 8 warps, then 64 global atomics
    // (4 g-blocks still share each row).
    *(float2*)&ldbuf[w_id * BM + r0] = make_float2(ld0, ld1);
    __syncthreads();
    if (t < BM) {
        float s = 0.0f;
#pragma unroll
        for (int w = 0; w < NGRP; w++) s += ldbuf[w * BM + t];
        atomicAdd(&out[(size_t)MROWS * 64 + rowbase + t], s);
    }
}

extern "C" void kernel_launch(void* const* d_in, const int* in_sizes, int n_in,
                              void* d_out, int out_size) {
    const float* c = (const float*)d_in[0];   // (65536, 16)
    const float* z = (const float*)d_in[1];   // (65536, 64)
    const float* W = (const float*)d_in[2];   // (48, 1056)
    const float* b = (const float*)d_in[3];   // (1056,)
    float* out = (float*)d_out;               // 65536*64 (x) + 65536 (log_det)

    cudaFuncSetAttribute(spline_main_kernel,
                         cudaFuncAttributeMaxDynamicSharedMemorySize, SMEM_BYTES);

    prep_kernel<<<(MROWS / 4 + 255) / 256, 256>>>(out);

    dim3 grid(NSPL / NGRP, MROWS / BM);       // (4, 1024)
    spline_main_kernel<<<grid, THREADS, SMEM_BYTES>>>(c, z, W, b, out);
}